// round 6
// baseline (speedup 1.0000x reference)
#include <cuda_runtime.h>
#include <math.h>

// ---------------- problem constants ----------------
#define Bn   256
#define Tn   512
#define INn  32
#define Hn   128
#define Sn   4
#define HQn  32
#define BTn  (Bn*Tn)          // 131072 positions
#define DTC  0.1f
#define LOG2E 1.4426950408889634f

typedef unsigned long long u64;
typedef ulonglong2 u64x2;

// ---------------- scratch (static device globals; no allocation) ----------------
__device__ float g_xp  [(size_t)BTn*Hn];        //  64 MB
__device__ float g_inp [(size_t)Sn*BTn*Hn];     // 268 MB (pair-interleaved channels)
__device__ float g_itau[(size_t)Sn*BTn*Hn];     // 268 MB (pair-interleaved channels)
__device__ float g_hT  [Sn*Bn*Hn];

// ---------------- packed fp32x2 helpers (Blackwell FFMA2) ----------------
__device__ __forceinline__ void ffma2(u64 &d, u64 a, u64 b) {
    asm("fma.rn.f32x2 %0, %1, %2, %0;" : "+l"(d) : "l"(a), "l"(b));
}
__device__ __forceinline__ void add2(u64 &d, u64 a) {
    asm("add.rn.f32x2 %0, %0, %1;" : "+l"(d) : "l"(a));
}
__device__ __forceinline__ float hsum1(u64 a0) {
    float x0, y0;
    asm("mov.b64 {%0,%1}, %2;" : "=f"(x0), "=f"(y0) : "l"(a0));
    return x0 + y0;
}
__device__ __forceinline__ float hsum2p(u64 a0, u64 a1) {
    add2(a0, a1);
    return hsum1(a0);
}
__device__ __forceinline__ float hsum4(u64 a0, u64 a1, u64 a2, u64 a3) {
    add2(a0, a1); add2(a2, a3); add2(a0, a2);
    return hsum1(a0);
}

// ---------------- fast approx math ----------------
__device__ __forceinline__ float fast_ex2(float x) {
    float r; asm("ex2.approx.f32 %0, %1;" : "=f"(r) : "f"(x)); return r;
}
__device__ __forceinline__ float fast_rcp(float x) {
    float r; asm("rcp.approx.f32 %0, %1;" : "=f"(r) : "f"(x)); return r;
}
__device__ __forceinline__ float fast_sqrt(float x) {
    float r; asm("sqrt.approx.f32 %0, %1;" : "=f"(r) : "f"(x)); return r;
}
// tanh(x) = 1 - 2/(e^{2x}+1)
__device__ __forceinline__ float fast_tanh(float x) {
    float xc = fminf(fmaxf(x, -12.f), 12.f);
    float e  = fast_ex2(xc * (2.f * LOG2E));
    return 1.f - 2.f * fast_rcp(e + 1.f);
}
__device__ __forceinline__ float fast_sigmoid(float z) {
    float zc = fminf(fmaxf(z, -30.f), 30.f);
    return fast_rcp(1.f + fast_ex2(-zc * LOG2E));
}

// ============================================================================
// K1: x_proj[pos, i] = x[pos, :32] @ Wp[i, :32] + bp[i]
// ============================================================================
__global__ void __launch_bounds__(128) k_xp(const float* __restrict__ x,
                                            const float* __restrict__ Wp,
                                            const float* __restrict__ bp) {
    const int i  = threadIdx.x;
    const int p0 = blockIdx.x * 32;
    __shared__ __align__(16) float xs[32][INn];

    const float4* src = (const float4*)(x + (size_t)p0 * INn);
    float4* dst = (float4*)&xs[0][0];
    dst[i]       = src[i];
    dst[i + 128] = src[i + 128];

    u64 w[16];
    {
        const u64x2* wq = (const u64x2*)(Wp + (size_t)i * INn);
#pragma unroll
        for (int m = 0; m < 8; m++) { u64x2 v = wq[m]; w[2*m] = v.x; w[2*m+1] = v.y; }
    }
    const float bias = bp[i];
    __syncthreads();

#pragma unroll 4
    for (int p = 0; p < 32; p++) {
        const u64x2* xq = (const u64x2*)&xs[p][0];
        u64 a0 = 0ull, a1 = 0ull, a2 = 0ull, a3 = 0ull;
#pragma unroll
        for (int m = 0; m < 8; m += 2) {
            u64x2 p0v = xq[m], p1v = xq[m+1];
            ffma2(a0, w[2*m],   p0v.x); ffma2(a1, w[2*m+1], p0v.y);
            ffma2(a2, w[2*m+2], p1v.x); ffma2(a3, w[2*m+3], p1v.y);
        }
        g_xp[(size_t)(p0 + p) * Hn + i] = hsum4(a0, a1, a2, a3) + bias;
    }
}

// ============================================================================
// K2: inp drive. 64 positions per CTA. Thread i computes channel
// c = ((i&1)<<6)|(i>>1) so the pair-interleaved store lands at +i (coalesced).
// ============================================================================
__global__ void __launch_bounds__(128) k_inp(const float* __restrict__ Win_w,
                                             const float* __restrict__ Win_b,
                                             const float* __restrict__ cbias) {
    const int i  = threadIdx.x;
    const int s  = blockIdx.y;
    const int p0 = blockIdx.x * 64;
    const int c  = ((i & 1) << 6) | (i >> 1);
    __shared__ __align__(16) float xs[64][Hn];   // 32 KB

    const float4* src = (const float4*)(g_xp + (size_t)p0 * Hn);
    float4* dst = (float4*)&xs[0][0];
#pragma unroll
    for (int r = i; r < 2048; r += 128) dst[r] = src[r];

    u64 w[64];
    {
        const u64x2* wq = (const u64x2*)(Win_w + ((size_t)s * Hn + c) * Hn);
#pragma unroll
        for (int m = 0; m < 32; m++) { u64x2 v = wq[m]; w[2*m] = v.x; w[2*m+1] = v.y; }
    }
    const float bias = Win_b[s * Hn + c] + cbias[s * Hn + c];
    __syncthreads();

    float* outp = g_inp + ((size_t)s * BTn + p0) * Hn + i;
#pragma unroll 2
    for (int p = 0; p < 64; p++) {
        const u64x2* xq = (const u64x2*)&xs[p][0];
        u64 a0 = 0ull, a1 = 0ull, a2 = 0ull, a3 = 0ull;
#pragma unroll
        for (int m = 0; m < 32; m += 2) {
            u64x2 p0v = xq[m], p1v = xq[m+1];
            ffma2(a0, w[2*m],   p0v.x); ffma2(a1, w[2*m+1], p0v.y);
            ffma2(a2, w[2*m+2], p1v.x); ffma2(a3, w[2*m+3], p1v.y);
        }
        __stwt(outp + (size_t)p * Hn, hsum4(a0, a1, a2, a3) + bias);
    }
}

// ============================================================================
// K3: volatility gate -> itau. 64 positions per CTA; stage-2 channel permuted
// like k_inp for coalesced pair-interleaved stores.
// ============================================================================
__global__ void __launch_bounds__(128) k_itau(const float* __restrict__ v1w,
                                              const float* __restrict__ v1b,
                                              const float* __restrict__ v2w,
                                              const float* __restrict__ v2b,
                                              const float* __restrict__ tau_base) {
    const int i  = threadIdx.x;
    const int s  = blockIdx.y;
    const int p0 = blockIdx.x * 64;
    __shared__ __align__(16) float xs[64][Hn];   // 32 KB
    __shared__ __align__(16) float gs[64][HQn];  //  8 KB

    const float4* src = (const float4*)(g_xp + (size_t)p0 * Hn);
    float4* dst = (float4*)&xs[0][0];
#pragma unroll
    for (int r = i; r < 2048; r += 128) dst[r] = src[r];
    __syncthreads();

    // ---- stage 1: g = relu(xp @ v1w.T + v1b); 4 groups x 16 positions ----
    {
        const int q   = i & 31;
        const int grp = i >> 5;
        u64 wv[64];
        const u64x2* wq = (const u64x2*)(v1w + ((size_t)s * HQn + q) * Hn);
#pragma unroll
        for (int m = 0; m < 32; m++) { u64x2 v = wq[m]; wv[2*m] = v.x; wv[2*m+1] = v.y; }
        const float b1 = v1b[s * HQn + q];
#pragma unroll 2
        for (int pp = 0; pp < 16; pp++) {
            const int p = grp * 16 + pp;
            const u64x2* xq = (const u64x2*)&xs[p][0];
            u64 a0 = 0ull, a1 = 0ull, a2 = 0ull, a3 = 0ull;
#pragma unroll
            for (int m = 0; m < 32; m += 2) {
                u64x2 p0v = xq[m], p1v = xq[m+1];
                ffma2(a0, wv[2*m],   p0v.x); ffma2(a1, wv[2*m+1], p0v.y);
                ffma2(a2, wv[2*m+2], p1v.x); ffma2(a3, wv[2*m+3], p1v.y);
            }
            gs[p][q] = fmaxf(hsum4(a0, a1, a2, a3) + b1, 0.f);
        }
    }
    __syncthreads();

    // ---- stage 2: vol -> itau (channel-permuted, coalesced store) ----
    {
        const int c = ((i & 1) << 6) | (i >> 1);
        u64 w2[16];
        const u64x2* wq = (const u64x2*)(v2w + ((size_t)s * Hn + c) * HQn);
#pragma unroll
        for (int m = 0; m < 8; m++) { u64x2 v = wq[m]; w2[2*m] = v.x; w2[2*m+1] = v.y; }
        const float b2 = v2b[s * Hn + c];
        const float tb = tau_base[s * Hn + c];
        float* outp = g_itau + ((size_t)s * BTn + p0) * Hn + i;
#pragma unroll 2
        for (int p = 0; p < 64; p++) {
            const u64x2* gq = (const u64x2*)&gs[p][0];
            u64 a0 = 0ull, a1 = 0ull, a2 = 0ull, a3 = 0ull;
#pragma unroll
            for (int m = 0; m < 8; m += 2) {
                u64x2 p0v = gq[m], p1v = gq[m+1];
                ffma2(a0, w2[2*m],   p0v.x); ffma2(a1, w2[2*m+1], p0v.y);
                ffma2(a2, w2[2*m+2], p1v.x); ffma2(a3, w2[2*m+3], p1v.y);
            }
            const float z   = hsum4(a0, a1, a2, a3) + b2;
            const float vol = fast_sigmoid(z);
            float tau = tb * (0.2f + 1.8f * (1.f - vol));
            tau = fminf(fmaxf(tau, 0.1f), 10.f);
            __stwt(outp + (size_t)p * Hn, 1.f / tau);
        }
    }
}

// ============================================================================
// K4: liquid-cell scan, incremental-g formulation. ONE barrier per inner step.
// Thread state: h (2 ch) and g = W.h (2 ch, duplicated across half-lanes).
//   z = g + inp; target = tanh(z); dh = (target - h)*itau   [pre-barrier]
//   write dh to smem + 2-shfl norm partials -> red          [pre-barrier]
//   barrier
//   mag from red (overlaps matvec); Gd = W.dh via split-K + shfl(16)
//   h += sc*dh;  g += sc*Gd
// dh_s and red are double-buffered so one barrier per step is race-free.
// ============================================================================
__global__ void __launch_bounds__(128, 3) k_scan(const float* __restrict__ Wrec) {
    const int bid  = blockIdx.x;
    const int s    = 3 - (bid >> 8);     // heavy scale first (LPT)
    const int b    = bid & 255;
    const int t    = threadIdx.x;
    const int wid  = t >> 5;
    const int lane = t & 31;
    const int half = lane >> 4;                 // K-half
    const int cc   = wid * 16 + (lane & 15);    // 0..63

    __shared__ __align__(16) float dhs[2][Hn];
    __shared__ __align__(16) float4 red[2][4];  // [buf][warp] -> 4 partials

    // two half-rows of Wrec in registers (channels cc and cc+64)
    u64 w1[32], w2[32];
    {
        const u64x2* wq1 = (const u64x2*)(Wrec + ((size_t)s * Hn + cc) * Hn + half * 64);
        const u64x2* wq2 = (const u64x2*)(Wrec + ((size_t)s * Hn + cc + 64) * Hn + half * 64);
#pragma unroll
        for (int m = 0; m < 16; m++) { u64x2 v = wq1[m]; w1[2*m] = v.x; w1[2*m+1] = v.y; }
#pragma unroll
        for (int m = 0; m < 16; m++) { u64x2 v = wq2[m]; w2[2*m] = v.x; w2[2*m+1] = v.y; }
    }

    float h1 = 0.f, h2 = 0.f;     // hidden state
    float g1 = 0.f, g2 = 0.f;     // g = W.h (full dot, duplicated per half)
    int buf = 0;
    const int nsteps = 3 + 2 * s;
    const float2* inp_ptr  = (const float2*)g_inp  + ((size_t)(s * Bn + b)) * Tn * 64 + cc;
    const float2* itau_ptr = (const float2*)g_itau + ((size_t)(s * Bn + b)) * Tn * 64 + cc;

    float2 inp  = __ldcs(inp_ptr);
    float2 itau = __ldcs(itau_ptr);
    for (int tt = 0; tt < Tn; tt++) {
        const int tn = (tt + 1 < Tn) ? tt + 1 : tt;
        const float2 ninp  = __ldcs(inp_ptr  + (size_t)tn * 64);
        const float2 nitau = __ldcs(itau_ptr + (size_t)tn * 64);

        for (int k = 0; k < nsteps; k++) {
            // pre-barrier: target, dh, norm partials
            const float t1 = fast_tanh(g1 + inp.x);
            const float t2 = fast_tanh(g2 + inp.y);
            const float dh1 = (t1 - h1) * itau.x;
            const float dh2 = (t2 - h2) * itau.y;
            float sq = fmaf(dh1, dh1, dh2 * dh2);
            sq += __shfl_xor_sync(0xffffffffu, sq, 1);
            sq += __shfl_xor_sync(0xffffffffu, sq, 2);
            if (half == 0) {
                dhs[buf][cc]      = dh1;
                dhs[buf][cc + 64] = dh2;
                if ((lane & 3) == 0) ((float*)&red[buf][wid])[lane >> 2] = sq;
            }
            __syncthreads();

            // mag path (overlaps matvec in the scoreboard)
            const float4 r0 = red[buf][0], r1 = red[buf][1];
            const float4 r2 = red[buf][2], r3 = red[buf][3];
            const float tot = (((r0.x + r0.y) + (r0.z + r0.w)) +
                               ((r1.x + r1.y) + (r1.z + r1.w))) +
                              (((r2.x + r2.y) + (r2.z + r2.w)) +
                               ((r3.x + r3.y) + (r3.z + r3.w)));
            const float sc = DTC * fast_rcp(fmaf(0.2f, fast_sqrt(tot), 1.f));

            // matvec over dh (split-K, partner combine via shfl 16)
            const u64x2* dq = (const u64x2*)(dhs[buf] + half * 64);
            u64 a0 = 0ull, a1 = 0ull, b0 = 0ull, b1 = 0ull;
#pragma unroll
            for (int m = 0; m < 16; m++) {
                u64x2 hv = dq[m];
                ffma2(a0, w1[2*m],   hv.x); ffma2(b0, w2[2*m],   hv.x);
                ffma2(a1, w1[2*m+1], hv.y); ffma2(b1, w2[2*m+1], hv.y);
            }
            float p1 = hsum2p(a0, a1);
            float p2 = hsum2p(b0, b1);
            const float Gd1 = p1 + __shfl_xor_sync(0xffffffffu, p1, 16);
            const float Gd2 = p2 + __shfl_xor_sync(0xffffffffu, p2, 16);

            h1 = fmaf(sc, dh1, h1);  h2 = fmaf(sc, dh2, h2);
            g1 = fmaf(sc, Gd1, g1);  g2 = fmaf(sc, Gd2, g2);
            buf ^= 1;
        }
        inp = ninp; itau = nitau;
    }
    if (half == 0) {
        g_hT[((size_t)(s * Bn + b)) * Hn + cc]      = h1;
        g_hT[((size_t)(s * Bn + b)) * Hn + cc + 64] = h2;
    }
}

// ============================================================================
// K5: projection heads + fusion MLP. One CTA per batch row.
// ============================================================================
__global__ void __launch_bounds__(128) k_head(const float* __restrict__ proj_w,
                                              const float* __restrict__ proj_b,
                                              const float* __restrict__ f1_w,
                                              const float* __restrict__ f1_b,
                                              const float* __restrict__ f2_w,
                                              const float* __restrict__ f2_b,
                                              const float* __restrict__ f3_w,
                                              const float* __restrict__ f3_b,
                                              float* __restrict__ out) {
    const int b = blockIdx.x;
    const int i = threadIdx.x;
    __shared__ float fs[Hn];
    __shared__ float h1s[Hn];
    __shared__ float h2s[64];
    __shared__ float rs[4];

    {
        const int s = i >> 5, q = i & 31;
        const float* hrow = g_hT + (size_t)(s * Bn + b) * Hn;
        const float* pw   = proj_w + (size_t)(s * 32 + q) * Hn;
        float acc = proj_b[s * 32 + q];
#pragma unroll 8
        for (int j = 0; j < Hn; j++) acc += hrow[j] * pw[j];
        fs[i] = acc;
    }
    __syncthreads();

    {
        const float* w1 = f1_w + (size_t)i * Hn;
        float acc = f1_b[i];
#pragma unroll 8
        for (int j = 0; j < Hn; j++) acc += fs[j] * w1[j];
        h1s[i] = fmaxf(acc, 0.f);
    }
    __syncthreads();

    if (i < 64) {
        const float* w2 = f2_w + (size_t)i * Hn;
        float acc = f2_b[i];
#pragma unroll 8
        for (int j = 0; j < Hn; j++) acc += h1s[j] * w2[j];
        h2s[i] = fmaxf(acc, 0.f);
    }
    __syncthreads();

    float pr = (i < 64) ? h2s[i] * f3_w[i] : 0.f;
#pragma unroll
    for (int off = 16; off; off >>= 1) pr += __shfl_xor_sync(0xffffffffu, pr, off);
    if ((i & 31) == 0) rs[i >> 5] = pr;
    __syncthreads();
    if (i == 0) out[b] = rs[0] + rs[1] + f3_b[0];
}

// ============================================================================
extern "C" void kernel_launch(void* const* d_in, const int* in_sizes, int n_in,
                              void* d_out, int out_size) {
    (void)in_sizes; (void)n_in; (void)out_size;
    const float* x        = (const float*)d_in[0];
    const float* Wp       = (const float*)d_in[1];
    const float* bp       = (const float*)d_in[2];
    const float* Wrec     = (const float*)d_in[3];
    const float* Win_w    = (const float*)d_in[4];
    const float* Win_b    = (const float*)d_in[5];
    const float* cbias    = (const float*)d_in[6];
    const float* tau_base = (const float*)d_in[7];
    const float* vg1_w    = (const float*)d_in[8];
    const float* vg1_b    = (const float*)d_in[9];
    const float* vg2_w    = (const float*)d_in[10];
    const float* vg2_b    = (const float*)d_in[11];
    const float* proj_w   = (const float*)d_in[12];
    const float* proj_b   = (const float*)d_in[13];
    const float* f1_w     = (const float*)d_in[14];
    const float* f1_b     = (const float*)d_in[15];
    const float* f2_w     = (const float*)d_in[16];
    const float* f2_b     = (const float*)d_in[17];
    const float* f3_w     = (const float*)d_in[18];
    const float* f3_b     = (const float*)d_in[19];
    float* out = (float*)d_out;

    k_xp  <<<BTn / 32, 128>>>(x, Wp, bp);
    k_inp <<<dim3(BTn / 64, Sn), 128>>>(Win_w, Win_b, cbias);
    k_itau<<<dim3(BTn / 64, Sn), 128>>>(vg1_w, vg1_b, vg2_w, vg2_b, tau_base);
    k_scan<<<Sn * Bn, 128>>>(Wrec);
    k_head<<<Bn, 128>>>(proj_w, proj_b, f1_w, f1_b, f2_w, f2_b, f3_w, f3_b, out);
}

// round 7
// speedup vs baseline: 1.0054x; 1.0054x over previous
#include <cuda_runtime.h>
#include <math.h>

// ---------------- problem constants ----------------
#define Bn   256
#define Tn   512
#define INn  32
#define Hn   128
#define Sn   4
#define HQn  32
#define BTn  (Bn*Tn)          // 131072 positions
#define DTC  0.1f
#define LOG2E 1.4426950408889634f

typedef unsigned long long u64;
typedef ulonglong2 u64x2;

// ---------------- scratch (static device globals; no allocation) ----------------
__device__ float g_xp  [(size_t)BTn*Hn];        //  64 MB
__device__ float g_inp [(size_t)Sn*BTn*Hn];     // 268 MB (quad-interleaved channels)
__device__ float g_itau[(size_t)Sn*BTn*Hn];     // 268 MB (quad-interleaved channels)
__device__ float g_hT  [Sn*Bn*Hn];

// channel permutation: slot p holds channel ((p&3)<<5)|(p>>2)
// (thread i in K2/K3 computes channel chan(i) and stores to slot i -> coalesced)

// ---------------- packed fp32x2 helpers (Blackwell FFMA2) ----------------
__device__ __forceinline__ void ffma2(u64 &d, u64 a, u64 b) {
    asm("fma.rn.f32x2 %0, %1, %2, %0;" : "+l"(d) : "l"(a), "l"(b));
}
__device__ __forceinline__ void add2(u64 &d, u64 a) {
    asm("add.rn.f32x2 %0, %0, %1;" : "+l"(d) : "l"(a));
}
__device__ __forceinline__ float hsum1(u64 a0) {
    float x0, y0;
    asm("mov.b64 {%0,%1}, %2;" : "=f"(x0), "=f"(y0) : "l"(a0));
    return x0 + y0;
}
__device__ __forceinline__ float hsum4(u64 a0, u64 a1, u64 a2, u64 a3) {
    add2(a0, a1); add2(a2, a3); add2(a0, a2);
    return hsum1(a0);
}
__device__ __forceinline__ u64 pack2(float lo, float hi) {
    u64 r; asm("mov.b64 %0, {%1,%2};" : "=l"(r) : "f"(lo), "f"(hi)); return r;
}

// ---------------- fast approx math ----------------
__device__ __forceinline__ float fast_ex2(float x) {
    float r; asm("ex2.approx.f32 %0, %1;" : "=f"(r) : "f"(x)); return r;
}
__device__ __forceinline__ float fast_rcp(float x) {
    float r; asm("rcp.approx.f32 %0, %1;" : "=f"(r) : "f"(x)); return r;
}
__device__ __forceinline__ float fast_sqrt(float x) {
    float r; asm("sqrt.approx.f32 %0, %1;" : "=f"(r) : "f"(x)); return r;
}
// tanh(x) = 1 - 2/(e^{2x}+1)
__device__ __forceinline__ float fast_tanh(float x) {
    float xc = fminf(fmaxf(x, -12.f), 12.f);
    float e  = fast_ex2(xc * (2.f * LOG2E));
    return 1.f - 2.f * fast_rcp(e + 1.f);
}
__device__ __forceinline__ float fast_sigmoid(float z) {
    float zc = fminf(fmaxf(z, -30.f), 30.f);
    return fast_rcp(1.f + fast_ex2(-zc * LOG2E));
}

// ============================================================================
// K1: x_proj[pos, i] = x[pos, :32] @ Wp[i, :32] + bp[i]
// ============================================================================
__global__ void __launch_bounds__(128) k_xp(const float* __restrict__ x,
                                            const float* __restrict__ Wp,
                                            const float* __restrict__ bp) {
    const int i  = threadIdx.x;
    const int p0 = blockIdx.x * 32;
    __shared__ __align__(16) float xs[32][INn];

    const float4* src = (const float4*)(x + (size_t)p0 * INn);
    float4* dst = (float4*)&xs[0][0];
    dst[i]       = src[i];
    dst[i + 128] = src[i + 128];

    u64 w[16];
    {
        const u64x2* wq = (const u64x2*)(Wp + (size_t)i * INn);
#pragma unroll
        for (int m = 0; m < 8; m++) { u64x2 v = wq[m]; w[2*m] = v.x; w[2*m+1] = v.y; }
    }
    const float bias = bp[i];
    __syncthreads();

#pragma unroll 4
    for (int p = 0; p < 32; p++) {
        const u64x2* xq = (const u64x2*)&xs[p][0];
        u64 a0 = 0ull, a1 = 0ull, a2 = 0ull, a3 = 0ull;
#pragma unroll
        for (int m = 0; m < 8; m += 2) {
            u64x2 p0v = xq[m], p1v = xq[m+1];
            ffma2(a0, w[2*m],   p0v.x); ffma2(a1, w[2*m+1], p0v.y);
            ffma2(a2, w[2*m+2], p1v.x); ffma2(a3, w[2*m+3], p1v.y);
        }
        g_xp[(size_t)(p0 + p) * Hn + i] = hsum4(a0, a1, a2, a3) + bias;
    }
}

// ============================================================================
// K2: inp drive. 64 positions/CTA. Thread i computes channel
// c = ((i&3)<<5)|(i>>2) and stores to slot i -> coalesced quad-interleave.
// ============================================================================
__global__ void __launch_bounds__(128) k_inp(const float* __restrict__ Win_w,
                                             const float* __restrict__ Win_b,
                                             const float* __restrict__ cbias) {
    const int i  = threadIdx.x;
    const int s  = blockIdx.y;
    const int p0 = blockIdx.x * 64;
    const int c  = ((i & 3) << 5) | (i >> 2);
    __shared__ __align__(16) float xs[64][Hn];   // 32 KB

    const float4* src = (const float4*)(g_xp + (size_t)p0 * Hn);
    float4* dst = (float4*)&xs[0][0];
#pragma unroll
    for (int r = i; r < 2048; r += 128) dst[r] = src[r];

    u64 w[64];
    {
        const u64x2* wq = (const u64x2*)(Win_w + ((size_t)s * Hn + c) * Hn);
#pragma unroll
        for (int m = 0; m < 32; m++) { u64x2 v = wq[m]; w[2*m] = v.x; w[2*m+1] = v.y; }
    }
    const float bias = Win_b[s * Hn + c] + cbias[s * Hn + c];
    __syncthreads();

    float* outp = g_inp + ((size_t)s * BTn + p0) * Hn + i;
#pragma unroll 2
    for (int p = 0; p < 64; p++) {
        const u64x2* xq = (const u64x2*)&xs[p][0];
        u64 a0 = 0ull, a1 = 0ull, a2 = 0ull, a3 = 0ull;
#pragma unroll
        for (int m = 0; m < 32; m += 2) {
            u64x2 p0v = xq[m], p1v = xq[m+1];
            ffma2(a0, w[2*m],   p0v.x); ffma2(a1, w[2*m+1], p0v.y);
            ffma2(a2, w[2*m+2], p1v.x); ffma2(a3, w[2*m+3], p1v.y);
        }
        __stwt(outp + (size_t)p * Hn, hsum4(a0, a1, a2, a3) + bias);
    }
}

// ============================================================================
// K3: volatility gate -> itau. 64 positions/CTA; stage-2 channel permuted
// like k_inp for coalesced quad-interleaved stores.
// ============================================================================
__global__ void __launch_bounds__(128) k_itau(const float* __restrict__ v1w,
                                              const float* __restrict__ v1b,
                                              const float* __restrict__ v2w,
                                              const float* __restrict__ v2b,
                                              const float* __restrict__ tau_base) {
    const int i  = threadIdx.x;
    const int s  = blockIdx.y;
    const int p0 = blockIdx.x * 64;
    __shared__ __align__(16) float xs[64][Hn];   // 32 KB
    __shared__ __align__(16) float gs[64][HQn];  //  8 KB

    const float4* src = (const float4*)(g_xp + (size_t)p0 * Hn);
    float4* dst = (float4*)&xs[0][0];
#pragma unroll
    for (int r = i; r < 2048; r += 128) dst[r] = src[r];
    __syncthreads();

    // ---- stage 1: g = relu(xp @ v1w.T + v1b); 4 groups x 16 positions ----
    {
        const int q   = i & 31;
        const int grp = i >> 5;
        u64 wv[64];
        const u64x2* wq = (const u64x2*)(v1w + ((size_t)s * HQn + q) * Hn);
#pragma unroll
        for (int m = 0; m < 32; m++) { u64x2 v = wq[m]; wv[2*m] = v.x; wv[2*m+1] = v.y; }
        const float b1 = v1b[s * HQn + q];
#pragma unroll 2
        for (int pp = 0; pp < 16; pp++) {
            const int p = grp * 16 + pp;
            const u64x2* xq = (const u64x2*)&xs[p][0];
            u64 a0 = 0ull, a1 = 0ull, a2 = 0ull, a3 = 0ull;
#pragma unroll
            for (int m = 0; m < 32; m += 2) {
                u64x2 p0v = xq[m], p1v = xq[m+1];
                ffma2(a0, wv[2*m],   p0v.x); ffma2(a1, wv[2*m+1], p0v.y);
                ffma2(a2, wv[2*m+2], p1v.x); ffma2(a3, wv[2*m+3], p1v.y);
            }
            gs[p][q] = fmaxf(hsum4(a0, a1, a2, a3) + b1, 0.f);
        }
    }
    __syncthreads();

    // ---- stage 2: vol -> itau (channel-permuted, coalesced store) ----
    {
        const int c = ((i & 3) << 5) | (i >> 2);
        u64 w2[16];
        const u64x2* wq = (const u64x2*)(v2w + ((size_t)s * Hn + c) * HQn);
#pragma unroll
        for (int m = 0; m < 8; m++) { u64x2 v = wq[m]; w2[2*m] = v.x; w2[2*m+1] = v.y; }
        const float b2 = v2b[s * Hn + c];
        const float tb = tau_base[s * Hn + c];
        float* outp = g_itau + ((size_t)s * BTn + p0) * Hn + i;
#pragma unroll 2
        for (int p = 0; p < 64; p++) {
            const u64x2* gq = (const u64x2*)&gs[p][0];
            u64 a0 = 0ull, a1 = 0ull, a2 = 0ull, a3 = 0ull;
#pragma unroll
            for (int m = 0; m < 8; m += 2) {
                u64x2 p0v = gq[m], p1v = gq[m+1];
                ffma2(a0, w2[2*m],   p0v.x); ffma2(a1, w2[2*m+1], p0v.y);
                ffma2(a2, w2[2*m+2], p1v.x); ffma2(a3, w2[2*m+3], p1v.y);
            }
            const float z   = hsum4(a0, a1, a2, a3) + b2;
            const float vol = fast_sigmoid(z);
            float tau = tb * (0.2f + 1.8f * (1.f - vol));
            tau = fminf(fmaxf(tau, 0.1f), 10.f);
            __stwt(outp + (size_t)p * Hn, 1.f / tau);
        }
    }
}

// ============================================================================
// K4: liquid-cell scan, 4-outputs-per-thread quarter-K.
// 128 threads. Thread (warp wd, lane l): q = l>>3 (K-quarter), cw = l&7,
// base channel cc = wd*8+cw. Owns channels {cc, cc+32, cc+64, cc+96} with
// h-range [q*32, q*32+32) in the permuted layout -> each h float serves
// 4 MACs (smem delivery 16KB/CTA-step, half of R5). Quarter combine via
// shfl_xor {8,16}; norm over cw bits via shfl_xor {1,2,4}. Two barriers/step
// (R5 structure, proven better than incremental-g).
// ============================================================================
__global__ void __launch_bounds__(128, 3) k_scan(const float* __restrict__ Wrec) {
    const int bid  = blockIdx.x;
    const int s    = 3 - (bid >> 8);     // heavy scale first (LPT)
    const int b    = bid & 255;
    const int t    = threadIdx.x;
    const int wd   = t >> 5;
    const int lane = t & 31;
    const int q    = lane >> 3;          // K-quarter
    const int cc   = wd * 8 + (lane & 7);  // base channel 0..31

    __shared__ __align__(16) float h_s[Hn];    // permuted layout
    __shared__ __align__(16) float red[4];

    // weights: 4 rows (cc+32r), permuted K positions q*32 .. q*32+31
    u64 w[4][16];
    {
        const float* Wb = Wrec + (size_t)s * Hn * Hn;
#pragma unroll
        for (int r = 0; r < 4; r++) {
            const float* row = Wb + (size_t)(cc + 32 * r) * Hn;
#pragma unroll
            for (int m = 0; m < 16; m++) {
                const int pA = q * 32 + 2 * m, pB = pA + 1;
                const float lo = row[((pA & 3) << 5) | (pA >> 2)];
                const float hi = row[((pB & 3) << 5) | (pB >> 2)];
                w[r][m] = pack2(lo, hi);
            }
        }
    }

    float h0 = 0.f, h1 = 0.f, h2 = 0.f, h3 = 0.f;
    h_s[t] = 0.f;
    const int nsteps = 3 + 2 * s;
    const float4* inp_ptr  = (const float4*)g_inp  + ((size_t)(s * Bn + b)) * Tn * 32 + cc;
    const float4* itau_ptr = (const float4*)g_itau + ((size_t)(s * Bn + b)) * Tn * 32 + cc;
    __syncthreads();

    float4 inp  = __ldcs(inp_ptr);
    float4 itau = __ldcs(itau_ptr);
    for (int tt = 0; tt < Tn; tt++) {
        const int tn = (tt + 1 < Tn) ? tt + 1 : tt;
        const float4 ninp  = __ldcs(inp_ptr  + (size_t)tn * 32);
        const float4 nitau = __ldcs(itau_ptr + (size_t)tn * 32);

        for (int k = 0; k < nsteps; k++) {
            // partial dots over this thread's 32 h-values, 4 output rows
            const u64x2* hq = (const u64x2*)(h_s + q * 32);
            u64 a0 = 0ull, a1 = 0ull, a2 = 0ull, a3 = 0ull;
#pragma unroll
            for (int m = 0; m < 8; m++) {
                const u64x2 hv = hq[m];
                ffma2(a0, w[0][2*m], hv.x); ffma2(a0, w[0][2*m+1], hv.y);
                ffma2(a1, w[1][2*m], hv.x); ffma2(a1, w[1][2*m+1], hv.y);
                ffma2(a2, w[2][2*m], hv.x); ffma2(a2, w[2][2*m+1], hv.y);
                ffma2(a3, w[3][2*m], hv.x); ffma2(a3, w[3][2*m+1], hv.y);
            }
            float p0 = hsum1(a0), p1 = hsum1(a1), p2 = hsum1(a2), p3 = hsum1(a3);
            // combine 4 K-quarters (butterfly -> all quarter replicas get full sum)
            p0 += __shfl_xor_sync(0xffffffffu, p0, 8);
            p1 += __shfl_xor_sync(0xffffffffu, p1, 8);
            p2 += __shfl_xor_sync(0xffffffffu, p2, 8);
            p3 += __shfl_xor_sync(0xffffffffu, p3, 8);
            p0 += __shfl_xor_sync(0xffffffffu, p0, 16);
            p1 += __shfl_xor_sync(0xffffffffu, p1, 16);
            p2 += __shfl_xor_sync(0xffffffffu, p2, 16);
            p3 += __shfl_xor_sync(0xffffffffu, p3, 16);

            const float dh0 = (fast_tanh(p0 + inp.x) - h0) * itau.x;
            const float dh1 = (fast_tanh(p1 + inp.y) - h1) * itau.y;
            const float dh2 = (fast_tanh(p2 + inp.z) - h2) * itau.z;
            const float dh3 = (fast_tanh(p3 + inp.w) - h3) * itau.w;

            // ||dhdt||^2: quarters duplicate -> reduce over cw bits {1,2,4}
            float sq = fmaf(dh0, dh0, fmaf(dh1, dh1, fmaf(dh2, dh2, dh3 * dh3)));
            sq += __shfl_xor_sync(0xffffffffu, sq, 1);
            sq += __shfl_xor_sync(0xffffffffu, sq, 2);
            sq += __shfl_xor_sync(0xffffffffu, sq, 4);
            if (lane == 0) red[wd] = sq;
            __syncthreads();
            const float4 r = *(const float4*)red;
            const float mag = fast_sqrt((r.x + r.y) + (r.z + r.w));
            const float sc  = DTC * fast_rcp(fmaf(0.2f, mag, 1.f));
            h0 = fmaf(sc, dh0, h0);
            h1 = fmaf(sc, dh1, h1);
            h2 = fmaf(sc, dh2, h2);
            h3 = fmaf(sc, dh3, h3);
            if (q == 0) ((float4*)h_s)[cc] = make_float4(h0, h1, h2, h3);
            __syncthreads();
        }
        inp = ninp; itau = nitau;
    }
    if (q == 0) {
        float* o = g_hT + ((size_t)(s * Bn + b)) * Hn;
        o[cc]      = h0;
        o[cc + 32] = h1;
        o[cc + 64] = h2;
        o[cc + 96] = h3;
    }
}

// ============================================================================
// K5: projection heads + fusion MLP. One CTA per batch row.
// ============================================================================
__global__ void __launch_bounds__(128) k_head(const float* __restrict__ proj_w,
                                              const float* __restrict__ proj_b,
                                              const float* __restrict__ f1_w,
                                              const float* __restrict__ f1_b,
                                              const float* __restrict__ f2_w,
                                              const float* __restrict__ f2_b,
                                              const float* __restrict__ f3_w,
                                              const float* __restrict__ f3_b,
                                              float* __restrict__ out) {
    const int b = blockIdx.x;
    const int i = threadIdx.x;
    __shared__ float fs[Hn];
    __shared__ float h1s[Hn];
    __shared__ float h2s[64];
    __shared__ float rs[4];

    {
        const int s = i >> 5, q = i & 31;
        const float* hrow = g_hT + (size_t)(s * Bn + b) * Hn;
        const float* pw   = proj_w + (size_t)(s * 32 + q) * Hn;
        float acc = proj_b[s * 32 + q];
#pragma unroll 8
        for (int j = 0; j < Hn; j++) acc += hrow[j] * pw[j];
        fs[i] = acc;
    }
    __syncthreads();

    {
        const float* w1 = f1_w + (size_t)i * Hn;
        float acc = f1_b[i];
#pragma unroll 8
        for (int j = 0; j < Hn; j++) acc += fs[j] * w1[j];
        h1s[i] = fmaxf(acc, 0.f);
    }
    __syncthreads();

    if (i < 64) {
        const float* w2 = f2_w + (size_t)i * Hn;
        float acc = f2_b[i];
#pragma unroll 8
        for (int j = 0; j < Hn; j++) acc += h1s[j] * w2[j];
        h2s[i] = fmaxf(acc, 0.f);
    }
    __syncthreads();

    float pr = (i < 64) ? h2s[i] * f3_w[i] : 0.f;
#pragma unroll
    for (int off = 16; off; off >>= 1) pr += __shfl_xor_sync(0xffffffffu, pr, off);
    if ((i & 31) == 0) rs[i >> 5] = pr;
    __syncthreads();
    if (i == 0) out[b] = rs[0] + rs[1] + f3_b[0];
}

// ============================================================================
extern "C" void kernel_launch(void* const* d_in, const int* in_sizes, int n_in,
                              void* d_out, int out_size) {
    (void)in_sizes; (void)n_in; (void)out_size;
    const float* x        = (const float*)d_in[0];
    const float* Wp       = (const float*)d_in[1];
    const float* bp       = (const float*)d_in[2];
    const float* Wrec     = (const float*)d_in[3];
    const float* Win_w    = (const float*)d_in[4];
    const float* Win_b    = (const float*)d_in[5];
    const float* cbias    = (const float*)d_in[6];
    const float* tau_base = (const float*)d_in[7];
    const float* vg1_w    = (const float*)d_in[8];
    const float* vg1_b    = (const float*)d_in[9];
    const float* vg2_w    = (const float*)d_in[10];
    const float* vg2_b    = (const float*)d_in[11];
    const float* proj_w   = (const float*)d_in[12];
    const float* proj_b   = (const float*)d_in[13];
    const float* f1_w     = (const float*)d_in[14];
    const float* f1_b     = (const float*)d_in[15];
    const float* f2_w     = (const float*)d_in[16];
    const float* f2_b     = (const float*)d_in[17];
    const float* f3_w     = (const float*)d_in[18];
    const float* f3_b     = (const float*)d_in[19];
    float* out = (float*)d_out;

    k_xp  <<<BTn / 32, 128>>>(x, Wp, bp);
    k_inp <<<dim3(BTn / 64, Sn), 128>>>(Win_w, Win_b, cbias);
    k_itau<<<dim3(BTn / 64, Sn), 128>>>(vg1_w, vg1_b, vg2_w, vg2_b, tau_base);
    k_scan<<<Sn * Bn, 128>>>(Wrec);
    k_head<<<Bn, 128>>>(proj_w, proj_b, f1_w, f1_b, f2_w, f2_b, f3_w, f3_b, out);
}

// round 8
// speedup vs baseline: 1.0860x; 1.0801x over previous
#include <cuda_runtime.h>
#include <math.h>

// ---------------- problem constants ----------------
#define Bn   256
#define Tn   512
#define INn  32
#define Hn   128
#define Sn   4
#define HQn  32
#define BTn  (Bn*Tn)          // 131072 positions
#define DTC  0.1f
#define LOG2E 1.4426950408889634f

typedef unsigned long long u64;
typedef ulonglong2 u64x2;

// ---------------- scratch (static device globals; no allocation) ----------------
__device__ float g_xp  [(size_t)BTn*Hn];        //  64 MB
__device__ float g_inp [(size_t)Sn*BTn*Hn];     // 268 MB (pair-interleaved channels)
__device__ float g_itau[(size_t)Sn*BTn*Hn];     // 268 MB (pair-interleaved channels)
__device__ float g_hT  [Sn*Bn*Hn];

// ---------------- packed fp32x2 helpers (Blackwell FFMA2) ----------------
__device__ __forceinline__ void ffma2(u64 &d, u64 a, u64 b) {
    asm("fma.rn.f32x2 %0, %1, %2, %0;" : "+l"(d) : "l"(a), "l"(b));
}
__device__ __forceinline__ void add2(u64 &d, u64 a) {
    asm("add.rn.f32x2 %0, %0, %1;" : "+l"(d) : "l"(a));
}
__device__ __forceinline__ float hsum1(u64 a0) {
    float x0, y0;
    asm("mov.b64 {%0,%1}, %2;" : "=f"(x0), "=f"(y0) : "l"(a0));
    return x0 + y0;
}
__device__ __forceinline__ float hsum2p(u64 a0, u64 a1) {
    add2(a0, a1);
    return hsum1(a0);
}
__device__ __forceinline__ float hsum4(u64 a0, u64 a1, u64 a2, u64 a3) {
    add2(a0, a1); add2(a2, a3); add2(a0, a2);
    return hsum1(a0);
}

// ---------------- fast approx math ----------------
__device__ __forceinline__ float fast_ex2(float x) {
    float r; asm("ex2.approx.f32 %0, %1;" : "=f"(r) : "f"(x)); return r;
}
__device__ __forceinline__ float fast_rcp(float x) {
    float r; asm("rcp.approx.f32 %0, %1;" : "=f"(r) : "f"(x)); return r;
}
__device__ __forceinline__ float fast_sqrt(float x) {
    float r; asm("sqrt.approx.f32 %0, %1;" : "=f"(r) : "f"(x)); return r;
}
// tanh(x) = 1 - 2/(e^{2x}+1)
__device__ __forceinline__ float fast_tanh(float x) {
    float xc = fminf(fmaxf(x, -12.f), 12.f);
    float e  = fast_ex2(xc * (2.f * LOG2E));
    return 1.f - 2.f * fast_rcp(e + 1.f);
}
__device__ __forceinline__ float fast_sigmoid(float z) {
    float zc = fminf(fmaxf(z, -30.f), 30.f);
    return fast_rcp(1.f + fast_ex2(-zc * LOG2E));
}

// ============================================================================
// K1: x_proj[pos, i] = x[pos, :32] @ Wp[i, :32] + bp[i]
// ============================================================================
__global__ void __launch_bounds__(128) k_xp(const float* __restrict__ x,
                                            const float* __restrict__ Wp,
                                            const float* __restrict__ bp) {
    const int i  = threadIdx.x;
    const int p0 = blockIdx.x * 32;
    __shared__ __align__(16) float xs[32][INn];

    const float4* src = (const float4*)(x + (size_t)p0 * INn);
    float4* dst = (float4*)&xs[0][0];
    dst[i]       = src[i];
    dst[i + 128] = src[i + 128];

    u64 w[16];
    {
        const u64x2* wq = (const u64x2*)(Wp + (size_t)i * INn);
#pragma unroll
        for (int m = 0; m < 8; m++) { u64x2 v = wq[m]; w[2*m] = v.x; w[2*m+1] = v.y; }
    }
    const float bias = bp[i];
    __syncthreads();

#pragma unroll 4
    for (int p = 0; p < 32; p++) {
        const u64x2* xq = (const u64x2*)&xs[p][0];
        u64 a0 = 0ull, a1 = 0ull, a2 = 0ull, a3 = 0ull;
#pragma unroll
        for (int m = 0; m < 8; m += 2) {
            u64x2 p0v = xq[m], p1v = xq[m+1];
            ffma2(a0, w[2*m],   p0v.x); ffma2(a1, w[2*m+1], p0v.y);
            ffma2(a2, w[2*m+2], p1v.x); ffma2(a3, w[2*m+3], p1v.y);
        }
        g_xp[(size_t)(p0 + p) * Hn + i] = hsum4(a0, a1, a2, a3) + bias;
    }
}

// ============================================================================
// K2: inp drive. 64 positions per CTA. Thread i computes channel
// c = ((i&1)<<6)|(i>>1) so the pair-interleaved store lands at +i (coalesced).
// ============================================================================
__global__ void __launch_bounds__(128) k_inp(const float* __restrict__ Win_w,
                                             const float* __restrict__ Win_b,
                                             const float* __restrict__ cbias) {
    const int i  = threadIdx.x;
    const int s  = blockIdx.y;
    const int p0 = blockIdx.x * 64;
    const int c  = ((i & 1) << 6) | (i >> 1);
    __shared__ __align__(16) float xs[64][Hn];   // 32 KB

    const float4* src = (const float4*)(g_xp + (size_t)p0 * Hn);
    float4* dst = (float4*)&xs[0][0];
#pragma unroll
    for (int r = i; r < 2048; r += 128) dst[r] = src[r];

    u64 w[64];
    {
        const u64x2* wq = (const u64x2*)(Win_w + ((size_t)s * Hn + c) * Hn);
#pragma unroll
        for (int m = 0; m < 32; m++) { u64x2 v = wq[m]; w[2*m] = v.x; w[2*m+1] = v.y; }
    }
    const float bias = Win_b[s * Hn + c] + cbias[s * Hn + c];
    __syncthreads();

    float* outp = g_inp + ((size_t)s * BTn + p0) * Hn + i;
#pragma unroll 2
    for (int p = 0; p < 64; p++) {
        const u64x2* xq = (const u64x2*)&xs[p][0];
        u64 a0 = 0ull, a1 = 0ull, a2 = 0ull, a3 = 0ull;
#pragma unroll
        for (int m = 0; m < 32; m += 2) {
            u64x2 p0v = xq[m], p1v = xq[m+1];
            ffma2(a0, w[2*m],   p0v.x); ffma2(a1, w[2*m+1], p0v.y);
            ffma2(a2, w[2*m+2], p1v.x); ffma2(a3, w[2*m+3], p1v.y);
        }
        __stwt(outp + (size_t)p * Hn, hsum4(a0, a1, a2, a3) + bias);
    }
}

// ============================================================================
// K3: volatility gate -> itau. 64 positions per CTA; stage-2 channel permuted
// like k_inp for coalesced pair-interleaved stores.
// ============================================================================
__global__ void __launch_bounds__(128) k_itau(const float* __restrict__ v1w,
                                              const float* __restrict__ v1b,
                                              const float* __restrict__ v2w,
                                              const float* __restrict__ v2b,
                                              const float* __restrict__ tau_base) {
    const int i  = threadIdx.x;
    const int s  = blockIdx.y;
    const int p0 = blockIdx.x * 64;
    __shared__ __align__(16) float xs[64][Hn];   // 32 KB
    __shared__ __align__(16) float gs[64][HQn];  //  8 KB

    const float4* src = (const float4*)(g_xp + (size_t)p0 * Hn);
    float4* dst = (float4*)&xs[0][0];
#pragma unroll
    for (int r = i; r < 2048; r += 128) dst[r] = src[r];
    __syncthreads();

    // ---- stage 1: g = relu(xp @ v1w.T + v1b); 4 groups x 16 positions ----
    {
        const int q   = i & 31;
        const int grp = i >> 5;
        u64 wv[64];
        const u64x2* wq = (const u64x2*)(v1w + ((size_t)s * HQn + q) * Hn);
#pragma unroll
        for (int m = 0; m < 32; m++) { u64x2 v = wq[m]; wv[2*m] = v.x; wv[2*m+1] = v.y; }
        const float b1 = v1b[s * HQn + q];
#pragma unroll 2
        for (int pp = 0; pp < 16; pp++) {
            const int p = grp * 16 + pp;
            const u64x2* xq = (const u64x2*)&xs[p][0];
            u64 a0 = 0ull, a1 = 0ull, a2 = 0ull, a3 = 0ull;
#pragma unroll
            for (int m = 0; m < 32; m += 2) {
                u64x2 p0v = xq[m], p1v = xq[m+1];
                ffma2(a0, wv[2*m],   p0v.x); ffma2(a1, wv[2*m+1], p0v.y);
                ffma2(a2, wv[2*m+2], p1v.x); ffma2(a3, wv[2*m+3], p1v.y);
            }
            gs[p][q] = fmaxf(hsum4(a0, a1, a2, a3) + b1, 0.f);
        }
    }
    __syncthreads();

    // ---- stage 2: vol -> itau (channel-permuted, coalesced store) ----
    {
        const int c = ((i & 1) << 6) | (i >> 1);
        u64 w2[16];
        const u64x2* wq = (const u64x2*)(v2w + ((size_t)s * Hn + c) * HQn);
#pragma unroll
        for (int m = 0; m < 8; m++) { u64x2 v = wq[m]; w2[2*m] = v.x; w2[2*m+1] = v.y; }
        const float b2 = v2b[s * Hn + c];
        const float tb = tau_base[s * Hn + c];
        float* outp = g_itau + ((size_t)s * BTn + p0) * Hn + i;
#pragma unroll 2
        for (int p = 0; p < 64; p++) {
            const u64x2* gq = (const u64x2*)&gs[p][0];
            u64 a0 = 0ull, a1 = 0ull, a2 = 0ull, a3 = 0ull;
#pragma unroll
            for (int m = 0; m < 8; m += 2) {
                u64x2 p0v = gq[m], p1v = gq[m+1];
                ffma2(a0, w2[2*m],   p0v.x); ffma2(a1, w2[2*m+1], p0v.y);
                ffma2(a2, w2[2*m+2], p1v.x); ffma2(a3, w2[2*m+3], p1v.y);
            }
            const float z   = hsum4(a0, a1, a2, a3) + b2;
            const float vol = fast_sigmoid(z);
            float tau = tb * (0.2f + 1.8f * (1.f - vol));
            tau = fminf(fmaxf(tau, 0.1f), 10.f);
            __stwt(outp + (size_t)p * Hn, 1.f / tau);
        }
    }
}

// ============================================================================
// K4: liquid-cell scan, DUAL-ROW version (R5 structure x 2 batch rows).
// One CTA = 2 batch rows of the same scale; Wrec registers are shared.
// Thread layout per row identical to R5: half = lane>>4, cc = wid*16+(lane&15),
// owns channels cc & cc+64, holds half-rows of Wrec (128 regs total).
// All per-row chains (LDS, FFMA2, shfl, tanh, norm) are independent and
// interleave -> 2x ILP hides the per-step latency; barriers shared.
// ============================================================================
__global__ void __launch_bounds__(128, 2) k_scan(const float* __restrict__ Wrec) {
    const int bid  = blockIdx.x;              // 0..511
    const int s    = 3 - (bid >> 7);          // heavy scale first (LPT)
    const int bp   = bid & 127;
    const int t    = threadIdx.x;
    const int wid  = t >> 5;
    const int lane = t & 31;
    const int half = lane >> 4;                 // K-half
    const int cc   = wid * 16 + (lane & 15);    // 0..63

    __shared__ __align__(16) float h_s[2][Hn];
    __shared__ __align__(16) float red[2][4];

    // two half-rows of Wrec in registers (channels cc and cc+64) — shared by both rows
    u64 w1[32], w2[32];
    {
        const u64x2* wq1 = (const u64x2*)(Wrec + ((size_t)s * Hn + cc) * Hn + half * 64);
        const u64x2* wq2 = (const u64x2*)(Wrec + ((size_t)s * Hn + cc + 64) * Hn + half * 64);
#pragma unroll
        for (int m = 0; m < 16; m++) { u64x2 v = wq1[m]; w1[2*m] = v.x; w1[2*m+1] = v.y; }
#pragma unroll
        for (int m = 0; m < 16; m++) { u64x2 v = wq2[m]; w2[2*m] = v.x; w2[2*m+1] = v.y; }
    }

    float hA1 = 0.f, hA2 = 0.f;   // row A state (channels cc, cc+64)
    float hB1 = 0.f, hB2 = 0.f;   // row B state
    h_s[0][t] = 0.f;
    h_s[1][t] = 0.f;
    const int nsteps = 3 + 2 * s;
    const size_t rowA = (size_t)(s * Bn + 2 * bp);
    const float2* inpA_p  = (const float2*)g_inp  + rowA * Tn * 64 + cc;
    const float2* itauA_p = (const float2*)g_itau + rowA * Tn * 64 + cc;
    const float2* inpB_p  = inpA_p  + (size_t)Tn * 64;
    const float2* itauB_p = itauA_p + (size_t)Tn * 64;
    __syncthreads();

    float2 inpA  = __ldcs(inpA_p),  inpB  = __ldcs(inpB_p);
    float2 itauA = __ldcs(itauA_p), itauB = __ldcs(itauB_p);
    for (int tt = 0; tt < Tn; tt++) {
        const int tn = (tt + 1 < Tn) ? tt + 1 : tt;
        const float2 ninpA  = __ldcs(inpA_p  + (size_t)tn * 64);
        const float2 nitauA = __ldcs(itauA_p + (size_t)tn * 64);
        const float2 ninpB  = __ldcs(inpB_p  + (size_t)tn * 64);
        const float2 nitauB = __ldcs(itauB_p + (size_t)tn * 64);

        for (int k = 0; k < nsteps; k++) {
            // interleaved partial dots: 2 rows x 2 output channels
            const u64x2* hqA = (const u64x2*)(h_s[0] + half * 64);
            const u64x2* hqB = (const u64x2*)(h_s[1] + half * 64);
            u64 a0 = 0ull, a1 = 0ull, b0 = 0ull, b1 = 0ull;
            u64 c0 = 0ull, c1 = 0ull, d0 = 0ull, d1 = 0ull;
#pragma unroll
            for (int m = 0; m < 16; m++) {
                const u64x2 hvA = hqA[m];
                const u64x2 hvB = hqB[m];
                ffma2(a0, w1[2*m],   hvA.x); ffma2(b0, w2[2*m],   hvA.x);
                ffma2(c0, w1[2*m],   hvB.x); ffma2(d0, w2[2*m],   hvB.x);
                ffma2(a1, w1[2*m+1], hvA.y); ffma2(b1, w2[2*m+1], hvA.y);
                ffma2(c1, w1[2*m+1], hvB.y); ffma2(d1, w2[2*m+1], hvB.y);
            }
            float pA1 = hsum2p(a0, a1);
            float pA2 = hsum2p(b0, b1);
            float pB1 = hsum2p(c0, c1);
            float pB2 = hsum2p(d0, d1);
            pA1 += __shfl_xor_sync(0xffffffffu, pA1, 16);
            pA2 += __shfl_xor_sync(0xffffffffu, pA2, 16);
            pB1 += __shfl_xor_sync(0xffffffffu, pB1, 16);
            pB2 += __shfl_xor_sync(0xffffffffu, pB2, 16);

            const float dhA1 = (fast_tanh(pA1 + inpA.x) - hA1) * itauA.x;
            const float dhA2 = (fast_tanh(pA2 + inpA.y) - hA2) * itauA.y;
            const float dhB1 = (fast_tanh(pB1 + inpB.x) - hB1) * itauB.x;
            const float dhB2 = (fast_tanh(pB2 + inpB.y) - hB2) * itauB.y;

            // norms: halves duplicate -> {1,2,4,8} per row, interleaved
            float sqA = fmaf(dhA1, dhA1, dhA2 * dhA2);
            float sqB = fmaf(dhB1, dhB1, dhB2 * dhB2);
            sqA += __shfl_xor_sync(0xffffffffu, sqA, 1);
            sqB += __shfl_xor_sync(0xffffffffu, sqB, 1);
            sqA += __shfl_xor_sync(0xffffffffu, sqA, 2);
            sqB += __shfl_xor_sync(0xffffffffu, sqB, 2);
            sqA += __shfl_xor_sync(0xffffffffu, sqA, 4);
            sqB += __shfl_xor_sync(0xffffffffu, sqB, 4);
            sqA += __shfl_xor_sync(0xffffffffu, sqA, 8);
            sqB += __shfl_xor_sync(0xffffffffu, sqB, 8);
            if (lane == 0) { red[0][wid] = sqA; red[1][wid] = sqB; }
            __syncthreads();
            const float4 rA = *(const float4*)red[0];
            const float4 rB = *(const float4*)red[1];
            const float magA = fast_sqrt((rA.x + rA.y) + (rA.z + rA.w));
            const float magB = fast_sqrt((rB.x + rB.y) + (rB.z + rB.w));
            const float scA = DTC * fast_rcp(fmaf(0.2f, magA, 1.f));
            const float scB = DTC * fast_rcp(fmaf(0.2f, magB, 1.f));
            hA1 = fmaf(scA, dhA1, hA1);  hA2 = fmaf(scA, dhA2, hA2);
            hB1 = fmaf(scB, dhB1, hB1);  hB2 = fmaf(scB, dhB2, hB2);
            if (half == 0) {
                h_s[0][cc] = hA1;  h_s[0][cc + 64] = hA2;
                h_s[1][cc] = hB1;  h_s[1][cc + 64] = hB2;
            }
            __syncthreads();
        }
        inpA = ninpA; itauA = nitauA;
        inpB = ninpB; itauB = nitauB;
    }
    if (half == 0) {
        float* oA = g_hT + rowA * Hn;
        oA[cc]           = hA1;
        oA[cc + 64]      = hA2;
        oA[Hn + cc]      = hB1;
        oA[Hn + cc + 64] = hB2;
    }
}

// ============================================================================
// K5: projection heads + fusion MLP. One CTA per batch row.
// ============================================================================
__global__ void __launch_bounds__(128) k_head(const float* __restrict__ proj_w,
                                              const float* __restrict__ proj_b,
                                              const float* __restrict__ f1_w,
                                              const float* __restrict__ f1_b,
                                              const float* __restrict__ f2_w,
                                              const float* __restrict__ f2_b,
                                              const float* __restrict__ f3_w,
                                              const float* __restrict__ f3_b,
                                              float* __restrict__ out) {
    const int b = blockIdx.x;
    const int i = threadIdx.x;
    __shared__ float fs[Hn];
    __shared__ float h1s[Hn];
    __shared__ float h2s[64];
    __shared__ float rs[4];

    {
        const int s = i >> 5, q = i & 31;
        const float* hrow = g_hT + (size_t)(s * Bn + b) * Hn;
        const float* pw   = proj_w + (size_t)(s * 32 + q) * Hn;
        float acc = proj_b[s * 32 + q];
#pragma unroll 8
        for (int j = 0; j < Hn; j++) acc += hrow[j] * pw[j];
        fs[i] = acc;
    }
    __syncthreads();

    {
        const float* w1 = f1_w + (size_t)i * Hn;
        float acc = f1_b[i];
#pragma unroll 8
        for (int j = 0; j < Hn; j++) acc += fs[j] * w1[j];
        h1s[i] = fmaxf(acc, 0.f);
    }
    __syncthreads();

    if (i < 64) {
        const float* w2 = f2_w + (size_t)i * Hn;
        float acc = f2_b[i];
#pragma unroll 8
        for (int j = 0; j < Hn; j++) acc += h1s[j] * w2[j];
        h2s[i] = fmaxf(acc, 0.f);
    }
    __syncthreads();

    float pr = (i < 64) ? h2s[i] * f3_w[i] : 0.f;
#pragma unroll
    for (int off = 16; off; off >>= 1) pr += __shfl_xor_sync(0xffffffffu, pr, off);
    if ((i & 31) == 0) rs[i >> 5] = pr;
    __syncthreads();
    if (i == 0) out[b] = rs[0] + rs[1] + f3_b[0];
}

// ============================================================================
extern "C" void kernel_launch(void* const* d_in, const int* in_sizes, int n_in,
                              void* d_out, int out_size) {
    (void)in_sizes; (void)n_in; (void)out_size;
    const float* x        = (const float*)d_in[0];
    const float* Wp       = (const float*)d_in[1];
    const float* bp       = (const float*)d_in[2];
    const float* Wrec     = (const float*)d_in[3];
    const float* Win_w    = (const float*)d_in[4];
    const float* Win_b    = (const float*)d_in[5];
    const float* cbias    = (const float*)d_in[6];
    const float* tau_base = (const float*)d_in[7];
    const float* vg1_w    = (const float*)d_in[8];
    const float* vg1_b    = (const float*)d_in[9];
    const float* vg2_w    = (const float*)d_in[10];
    const float* vg2_b    = (const float*)d_in[11];
    const float* proj_w   = (const float*)d_in[12];
    const float* proj_b   = (const float*)d_in[13];
    const float* f1_w     = (const float*)d_in[14];
    const float* f1_b     = (const float*)d_in[15];
    const float* f2_w     = (const float*)d_in[16];
    const float* f2_b     = (const float*)d_in[17];
    const float* f3_w     = (const float*)d_in[18];
    const float* f3_b     = (const float*)d_in[19];
    float* out = (float*)d_out;

    k_xp  <<<BTn / 32, 128>>>(x, Wp, bp);
    k_inp <<<dim3(BTn / 64, Sn), 128>>>(Win_w, Win_b, cbias);
    k_itau<<<dim3(BTn / 64, Sn), 128>>>(vg1_w, vg1_b, vg2_w, vg2_b, tau_base);
    k_scan<<<Sn * Bn / 2, 128>>>(Wrec);
    k_head<<<Bn, 128>>>(proj_w, proj_b, f1_w, f1_b, f2_w, f2_b, f3_w, f3_b, out);
}

// round 9
// speedup vs baseline: 1.2455x; 1.1469x over previous
#include <cuda_runtime.h>
#include <math.h>

// ---------------- problem constants ----------------
#define Bn   256
#define Tn   512
#define INn  32
#define Hn   128
#define Sn   4
#define HQn  32
#define BTn  (Bn*Tn)          // 131072 positions
#define DTC  0.1f
#define LOG2E 1.4426950408889634f

typedef unsigned long long u64;
typedef ulonglong2 u64x2;

// ---------------- scratch (static device globals; no allocation) ----------------
__device__ float g_xp  [(size_t)BTn*Hn];        //  64 MB
__device__ float g_inp [(size_t)Sn*BTn*Hn];     // 268 MB (pair-interleaved channels)
__device__ float g_itau[(size_t)Sn*BTn*Hn];     // 268 MB (pair-interleaved channels)
__device__ float g_hT  [Sn*Bn*Hn];

// ---------------- packed fp32x2 helpers (Blackwell FFMA2) ----------------
__device__ __forceinline__ void ffma2(u64 &d, u64 a, u64 b) {
    asm("fma.rn.f32x2 %0, %1, %2, %0;" : "+l"(d) : "l"(a), "l"(b));
}
__device__ __forceinline__ void add2(u64 &d, u64 a) {
    asm("add.rn.f32x2 %0, %0, %1;" : "+l"(d) : "l"(a));
}
__device__ __forceinline__ float hsum1(u64 a0) {
    float x0, y0;
    asm("mov.b64 {%0,%1}, %2;" : "=f"(x0), "=f"(y0) : "l"(a0));
    return x0 + y0;
}
__device__ __forceinline__ float hsum2p(u64 a0, u64 a1) {
    add2(a0, a1);
    return hsum1(a0);
}
__device__ __forceinline__ float hsum4(u64 a0, u64 a1, u64 a2, u64 a3) {
    add2(a0, a1); add2(a2, a3); add2(a0, a2);
    return hsum1(a0);
}

// ---------------- fast approx math ----------------
__device__ __forceinline__ float fast_ex2(float x) {
    float r; asm("ex2.approx.f32 %0, %1;" : "=f"(r) : "f"(x)); return r;
}
__device__ __forceinline__ float fast_rcp(float x) {
    float r; asm("rcp.approx.f32 %0, %1;" : "=f"(r) : "f"(x)); return r;
}
__device__ __forceinline__ float fast_sqrt(float x) {
    float r; asm("sqrt.approx.f32 %0, %1;" : "=f"(r) : "f"(x)); return r;
}
// single-op MUFU tanh (sm_75+): ~16cy, abs err ~6e-4
__device__ __forceinline__ float tanh_mufu(float x) {
    float r; asm("tanh.approx.f32 %0, %1;" : "=f"(r) : "f"(x)); return r;
}
__device__ __forceinline__ float fast_sigmoid(float z) {
    float zc = fminf(fmaxf(z, -30.f), 30.f);
    return fast_rcp(1.f + fast_ex2(-zc * LOG2E));
}

// ============================================================================
// K1: x_proj[pos, i] = x[pos, :32] @ Wp[i, :32] + bp[i]
// ============================================================================
__global__ void __launch_bounds__(128) k_xp(const float* __restrict__ x,
                                            const float* __restrict__ Wp,
                                            const float* __restrict__ bp) {
    const int i  = threadIdx.x;
    const int p0 = blockIdx.x * 32;
    __shared__ __align__(16) float xs[32][INn];

    const float4* src = (const float4*)(x + (size_t)p0 * INn);
    float4* dst = (float4*)&xs[0][0];
    dst[i]       = src[i];
    dst[i + 128] = src[i + 128];

    u64 w[16];
    {
        const u64x2* wq = (const u64x2*)(Wp + (size_t)i * INn);
#pragma unroll
        for (int m = 0; m < 8; m++) { u64x2 v = wq[m]; w[2*m] = v.x; w[2*m+1] = v.y; }
    }
    const float bias = bp[i];
    __syncthreads();

#pragma unroll 4
    for (int p = 0; p < 32; p++) {
        const u64x2* xq = (const u64x2*)&xs[p][0];
        u64 a0 = 0ull, a1 = 0ull, a2 = 0ull, a3 = 0ull;
#pragma unroll
        for (int m = 0; m < 8; m += 2) {
            u64x2 p0v = xq[m], p1v = xq[m+1];
            ffma2(a0, w[2*m],   p0v.x); ffma2(a1, w[2*m+1], p0v.y);
            ffma2(a2, w[2*m+2], p1v.x); ffma2(a3, w[2*m+3], p1v.y);
        }
        g_xp[(size_t)(p0 + p) * Hn + i] = hsum4(a0, a1, a2, a3) + bias;
    }
}

// ============================================================================
// K2: inp drive, split-K dual-channel.
// Thread (warp w, lane l): half = l>>4, c = w*16 + (l&15)  (0..63).
// Computes channels c and c+64 over K-half [half*64, half*64+64).
// shfl_xor(16) combines halves; half==0 lanes store a coalesced float2 at
// slots (2c, 2c+1)  == pair-interleaved layout the scan expects.
// Per-thread LDS per position: 16 LDS.128 (was 32); FLOPs unchanged.
// ============================================================================
__global__ void __launch_bounds__(128) k_inp(const float* __restrict__ Win_w,
                                             const float* __restrict__ Win_b,
                                             const float* __restrict__ cbias) {
    const int i    = threadIdx.x;
    const int s    = blockIdx.y;
    const int p0   = blockIdx.x * 64;
    const int wd   = i >> 5;
    const int lane = i & 31;
    const int half = lane >> 4;
    const int c    = wd * 16 + (lane & 15);   // 0..63
    __shared__ __align__(16) float xs[64][Hn];   // 32 KB

    const float4* src = (const float4*)(g_xp + (size_t)p0 * Hn);
    float4* dst = (float4*)&xs[0][0];
#pragma unroll
    for (int r = i; r < 2048; r += 128) dst[r] = src[r];

    u64 wA[32], wB[32];
    {
        const u64x2* wqA = (const u64x2*)(Win_w + ((size_t)s * Hn + c) * Hn + half * 64);
        const u64x2* wqB = (const u64x2*)(Win_w + ((size_t)s * Hn + c + 64) * Hn + half * 64);
#pragma unroll
        for (int m = 0; m < 16; m++) { u64x2 v = wqA[m]; wA[2*m] = v.x; wA[2*m+1] = v.y; }
#pragma unroll
        for (int m = 0; m < 16; m++) { u64x2 v = wqB[m]; wB[2*m] = v.x; wB[2*m+1] = v.y; }
    }
    const float biasA = Win_b[s * Hn + c]      + cbias[s * Hn + c];
    const float biasB = Win_b[s * Hn + c + 64] + cbias[s * Hn + c + 64];
    __syncthreads();

    float* outp = g_inp + ((size_t)s * BTn + p0) * Hn + 2 * c;
#pragma unroll 2
    for (int p = 0; p < 64; p++) {
        const u64x2* xq = (const u64x2*)(&xs[p][half * 64]);
        u64 a0 = 0ull, a1 = 0ull, b0 = 0ull, b1 = 0ull;
#pragma unroll
        for (int m = 0; m < 16; m++) {
            const u64x2 hv = xq[m];
            ffma2(a0, wA[2*m],   hv.x); ffma2(b0, wB[2*m],   hv.x);
            ffma2(a1, wA[2*m+1], hv.y); ffma2(b1, wB[2*m+1], hv.y);
        }
        float pA = hsum2p(a0, a1);
        float pB = hsum2p(b0, b1);
        pA += __shfl_xor_sync(0xffffffffu, pA, 16);
        pB += __shfl_xor_sync(0xffffffffu, pB, 16);
        if (half == 0) {
            float2 v = make_float2(pA + biasA, pB + biasB);
            __stwt((float2*)(outp + (size_t)p * Hn), v);
        }
    }
}

// ============================================================================
// K3: volatility gate -> itau. Stage 1 uses the same split-K dual-output
// trick (outputs q, q+16 over K-half). Stage 2 unchanged (K=32 is small).
// ============================================================================
__global__ void __launch_bounds__(128) k_itau(const float* __restrict__ v1w,
                                              const float* __restrict__ v1b,
                                              const float* __restrict__ v2w,
                                              const float* __restrict__ v2b,
                                              const float* __restrict__ tau_base) {
    const int i    = threadIdx.x;
    const int s    = blockIdx.y;
    const int p0   = blockIdx.x * 64;
    const int wd   = i >> 5;
    const int lane = i & 31;
    __shared__ __align__(16) float xs[64][Hn];   // 32 KB
    __shared__ __align__(16) float gs[64][HQn];  //  8 KB

    const float4* src = (const float4*)(g_xp + (size_t)p0 * Hn);
    float4* dst = (float4*)&xs[0][0];
#pragma unroll
    for (int r = i; r < 2048; r += 128) dst[r] = src[r];
    __syncthreads();

    // ---- stage 1: g = relu(xp @ v1w.T + v1b) ----
    // warp wd -> positions [wd*16, wd*16+16); lane: half=l>>4, q=(l&15);
    // thread computes outputs q and q+16 over K-half.
    {
        const int half = lane >> 4;
        const int q    = lane & 15;
        u64 wA[32], wB[32];
        const u64x2* wqA = (const u64x2*)(v1w + ((size_t)s * HQn + q) * Hn + half * 64);
        const u64x2* wqB = (const u64x2*)(v1w + ((size_t)s * HQn + q + 16) * Hn + half * 64);
#pragma unroll
        for (int m = 0; m < 16; m++) { u64x2 v = wqA[m]; wA[2*m] = v.x; wA[2*m+1] = v.y; }
#pragma unroll
        for (int m = 0; m < 16; m++) { u64x2 v = wqB[m]; wB[2*m] = v.x; wB[2*m+1] = v.y; }
        const float b1A = v1b[s * HQn + q];
        const float b1B = v1b[s * HQn + q + 16];
#pragma unroll 2
        for (int pp = 0; pp < 16; pp++) {
            const int p = wd * 16 + pp;
            const u64x2* xq = (const u64x2*)(&xs[p][half * 64]);
            u64 a0 = 0ull, a1 = 0ull, b0 = 0ull, b1 = 0ull;
#pragma unroll
            for (int m = 0; m < 16; m++) {
                const u64x2 hv = xq[m];
                ffma2(a0, wA[2*m],   hv.x); ffma2(b0, wB[2*m],   hv.x);
                ffma2(a1, wA[2*m+1], hv.y); ffma2(b1, wB[2*m+1], hv.y);
            }
            float pA = hsum2p(a0, a1);
            float pB = hsum2p(b0, b1);
            pA += __shfl_xor_sync(0xffffffffu, pA, 16);
            pB += __shfl_xor_sync(0xffffffffu, pB, 16);
            if (half == 0) {
                gs[p][q]      = fmaxf(pA + b1A, 0.f);
                gs[p][q + 16] = fmaxf(pB + b1B, 0.f);
            }
        }
    }
    __syncthreads();

    // ---- stage 2: vol -> itau (channel-permuted, coalesced store) ----
    {
        const int c = ((i & 1) << 6) | (i >> 1);
        u64 w2[16];
        const u64x2* wq = (const u64x2*)(v2w + ((size_t)s * Hn + c) * HQn);
#pragma unroll
        for (int m = 0; m < 8; m++) { u64x2 v = wq[m]; w2[2*m] = v.x; w2[2*m+1] = v.y; }
        const float b2 = v2b[s * Hn + c];
        const float tb = tau_base[s * Hn + c];
        float* outp = g_itau + ((size_t)s * BTn + p0) * Hn + i;
#pragma unroll 2
        for (int p = 0; p < 64; p++) {
            const u64x2* gq = (const u64x2*)&gs[p][0];
            u64 a0 = 0ull, a1 = 0ull, a2 = 0ull, a3 = 0ull;
#pragma unroll
            for (int m = 0; m < 8; m += 2) {
                u64x2 p0v = gq[m], p1v = gq[m+1];
                ffma2(a0, w2[2*m],   p0v.x); ffma2(a1, w2[2*m+1], p0v.y);
                ffma2(a2, w2[2*m+2], p1v.x); ffma2(a3, w2[2*m+3], p1v.y);
            }
            const float z   = hsum4(a0, a1, a2, a3) + b2;
            const float vol = fast_sigmoid(z);
            float tau = tb * (0.2f + 1.8f * (1.f - vol));
            tau = fminf(fmaxf(tau, 0.1f), 10.f);
            __stwt(outp + (size_t)p * Hn, 1.f / tau);
        }
    }
}

// ============================================================================
// K4: liquid-cell scan — R5 structure (measured best) + MUFU tanh.
// 128 threads; thread (warp wid, lane l): half = l>>4, cc = wid*16+(l&15).
// Owns channels cc & cc+64 over K-half; Wrec half-rows in 128 regs.
// 3 CTAs/SM; LPT (s=3 first); 2 barriers/step (cheap, defer-blocking).
// ============================================================================
__global__ void __launch_bounds__(128, 3) k_scan(const float* __restrict__ Wrec) {
    const int bid  = blockIdx.x;
    const int s    = 3 - (bid >> 8);     // heavy scale first (LPT)
    const int b    = bid & 255;
    const int t    = threadIdx.x;
    const int wid  = t >> 5;
    const int lane = t & 31;
    const int half = lane >> 4;                 // K-half
    const int cc   = wid * 16 + (lane & 15);    // 0..63

    __shared__ __align__(16) float h_s[Hn];
    __shared__ __align__(16) float red[4];

    // two half-rows of Wrec in registers
    u64 w1[32], w2[32];
    {
        const u64x2* wq1 = (const u64x2*)(Wrec + ((size_t)s * Hn + cc) * Hn + half * 64);
        const u64x2* wq2 = (const u64x2*)(Wrec + ((size_t)s * Hn + cc + 64) * Hn + half * 64);
#pragma unroll
        for (int m = 0; m < 16; m++) { u64x2 v = wq1[m]; w1[2*m] = v.x; w1[2*m+1] = v.y; }
#pragma unroll
        for (int m = 0; m < 16; m++) { u64x2 v = wq2[m]; w2[2*m] = v.x; w2[2*m+1] = v.y; }
    }

    float h1 = 0.f, h2 = 0.f;
    h_s[t] = 0.f;
    const int nsteps = 3 + 2 * s;
    const float2* inp_ptr  = (const float2*)g_inp  + ((size_t)(s * Bn + b)) * Tn * 64 + cc;
    const float2* itau_ptr = (const float2*)g_itau + ((size_t)(s * Bn + b)) * Tn * 64 + cc;
    __syncthreads();

    float2 inp  = __ldcs(inp_ptr);
    float2 itau = __ldcs(itau_ptr);
    for (int tt = 0; tt < Tn; tt++) {
        const int tn = (tt + 1 < Tn) ? tt + 1 : tt;
        const float2 ninp  = __ldcs(inp_ptr  + (size_t)tn * 64);
        const float2 nitau = __ldcs(itau_ptr + (size_t)tn * 64);

        for (int k = 0; k < nsteps; k++) {
            // partial dots over this thread's 64 h-values, 2 output channels
            const u64x2* hq = (const u64x2*)(h_s + half * 64);
            u64 a0 = 0ull, a1 = 0ull, b0 = 0ull, b1 = 0ull;
#pragma unroll
            for (int m = 0; m < 16; m++) {
                const u64x2 hv = hq[m];
                ffma2(a0, w1[2*m],   hv.x); ffma2(b0, w2[2*m],   hv.x);
                ffma2(a1, w1[2*m+1], hv.y); ffma2(b1, w2[2*m+1], hv.y);
            }
            float p1 = hsum2p(a0, a1);
            float p2 = hsum2p(b0, b1);
            const float z1 = p1 + __shfl_xor_sync(0xffffffffu, p1, 16) + inp.x;
            const float z2 = p2 + __shfl_xor_sync(0xffffffffu, p2, 16) + inp.y;

            const float dh1 = (tanh_mufu(z1) - h1) * itau.x;
            const float dh2 = (tanh_mufu(z2) - h2) * itau.y;

            // ||dhdt||^2: halves duplicate -> {1,2,4,8} sums 32 channels/warp
            float sq = fmaf(dh1, dh1, dh2 * dh2);
            sq += __shfl_xor_sync(0xffffffffu, sq, 1);
            sq += __shfl_xor_sync(0xffffffffu, sq, 2);
            sq += __shfl_xor_sync(0xffffffffu, sq, 4);
            sq += __shfl_xor_sync(0xffffffffu, sq, 8);
            if (lane == 0) red[wid] = sq;
            __syncthreads();
            const float4 r = *(const float4*)red;
            const float mag = fast_sqrt((r.x + r.y) + (r.z + r.w));
            const float sc  = DTC * fast_rcp(fmaf(0.2f, mag, 1.f));
            h1 = fmaf(sc, dh1, h1);
            h2 = fmaf(sc, dh2, h2);
            if (half == 0) { h_s[cc] = h1; h_s[cc + 64] = h2; }
            __syncthreads();
        }
        inp = ninp; itau = nitau;
    }
    if (half == 0) {
        g_hT[((size_t)(s * Bn + b)) * Hn + cc]      = h1;
        g_hT[((size_t)(s * Bn + b)) * Hn + cc + 64] = h2;
    }
}

// ============================================================================
// K5: projection heads + fusion MLP. One CTA per batch row.
// ============================================================================
__global__ void __launch_bounds__(128) k_head(const float* __restrict__ proj_w,
                                              const float* __restrict__ proj_b,
                                              const float* __restrict__ f1_w,
                                              const float* __restrict__ f1_b,
                                              const float* __restrict__ f2_w,
                                              const float* __restrict__ f2_b,
                                              const float* __restrict__ f3_w,
                                              const float* __restrict__ f3_b,
                                              float* __restrict__ out) {
    const int b = blockIdx.x;
    const int i = threadIdx.x;
    __shared__ float fs[Hn];
    __shared__ float h1s[Hn];
    __shared__ float h2s[64];
    __shared__ float rs[4];

    {
        const int s = i >> 5, q = i & 31;
        const float* hrow = g_hT + (size_t)(s * Bn + b) * Hn;
        const float* pw   = proj_w + (size_t)(s * 32 + q) * Hn;
        float acc = proj_b[s * 32 + q];
#pragma unroll 8
        for (int j = 0; j < Hn; j++) acc += hrow[j] * pw[j];
        fs[i] = acc;
    }
    __syncthreads();

    {
        const float* w1 = f1_w + (size_t)i * Hn;
        float acc = f1_b[i];
#pragma unroll 8
        for (int j = 0; j < Hn; j++) acc += fs[j] * w1[j];
        h1s[i] = fmaxf(acc, 0.f);
    }
    __syncthreads();

    if (i < 64) {
        const float* w2 = f2_w + (size_t)i * Hn;
        float acc = f2_b[i];
#pragma unroll 8
        for (int j = 0; j < Hn; j++) acc += h1s[j] * w2[j];
        h2s[i] = fmaxf(acc, 0.f);
    }
    __syncthreads();

    float pr = (i < 64) ? h2s[i] * f3_w[i] : 0.f;
#pragma unroll
    for (int off = 16; off; off >>= 1) pr += __shfl_xor_sync(0xffffffffu, pr, off);
    if ((i & 31) == 0) rs[i >> 5] = pr;
    __syncthreads();
    if (i == 0) out[b] = rs[0] + rs[1] + f3_b[0];
}

// ============================================================================
extern "C" void kernel_launch(void* const* d_in, const int* in_sizes, int n_in,
                              void* d_out, int out_size) {
    (void)in_sizes; (void)n_in; (void)out_size;
    const float* x        = (const float*)d_in[0];
    const float* Wp       = (const float*)d_in[1];
    const float* bp       = (const float*)d_in[2];
    const float* Wrec     = (const float*)d_in[3];
    const float* Win_w    = (const float*)d_in[4];
    const float* Win_b    = (const float*)d_in[5];
    const float* cbias    = (const float*)d_in[6];
    const float* tau_base = (const float*)d_in[7];
    const float* vg1_w    = (const float*)d_in[8];
    const float* vg1_b    = (const float*)d_in[9];
    const float* vg2_w    = (const float*)d_in[10];
    const float* vg2_b    = (const float*)d_in[11];
    const float* proj_w   = (const float*)d_in[12];
    const float* proj_b   = (const float*)d_in[13];
    const float* f1_w     = (const float*)d_in[14];
    const float* f1_b     = (const float*)d_in[15];
    const float* f2_w     = (const float*)d_in[16];
    const float* f2_b     = (const float*)d_in[17];
    const float* f3_w     = (const float*)d_in[18];
    const float* f3_b     = (const float*)d_in[19];
    float* out = (float*)d_out;

    k_xp  <<<BTn / 32, 128>>>(x, Wp, bp);
    k_inp <<<dim3(BTn / 64, Sn), 128>>>(Win_w, Win_b, cbias);
    k_itau<<<dim3(BTn / 64, Sn), 128>>>(vg1_w, vg1_b, vg2_w, vg2_b, tau_base);
    k_scan<<<Sn * Bn, 128>>>(Wrec);
    k_head<<<Bn, 128>>>(proj_w, proj_b, f1_w, f1_b, f2_w, f2_b, f3_w, f3_b, out);
}